// round 3
// baseline (speedup 1.0000x reference)
#include <cuda_runtime.h>
#include <mma.h>
#include <cstdint>

using namespace nvcuda;

#define BATCH   8
#define C       384
#define M4      1536
#define NZ      256
#define NX      1024
#define NT      1280
#define NHEADS  12
#define DHEAD   32
#define KDIM    384

// ---------------------------------------------------------------------------
// Scratch (static device globals)
// ---------------------------------------------------------------------------
__device__ float g_qkvo[BATCH * M4 * NT];   // [b][1536][1280] (z cols 0-255, x cols 256-1279)
__device__ float g_lepe[BATCH * C * NT];
__device__ float g_att [BATCH * C * NT];

// ---------------------------------------------------------------------------
// wmma tf32 GEMM: qkvo = W(1536x384) @ feat(384xHW) per batch
// block 256 thr = 8 warps; CTA tile 128x128; warp tile 64x32; K-chunk 32
// ---------------------------------------------------------------------------
#define LDA_S 36
#define LDB_S 132

__global__ __launch_bounds__(256) void qkvo_wmma_kernel(
    const float* __restrict__ feat, int HW, int seg,
    const float* __restrict__ W, const float* __restrict__ bias)
{
    __shared__ float As[128 * LDA_S];
    __shared__ float Bs[32 * LDB_S];
    __shared__ float bias_sm[128];
    __shared__ float scr[8 * 256];

    const int t = threadIdx.x, wid = t >> 5, lane = t & 31;
    const int m0 = blockIdx.x * 128, n0 = blockIdx.y * 128, b = blockIdx.z;
    const float* fb = feat + (size_t)b * KDIM * HW;

    if (t < 128) bias_sm[t] = bias[m0 + t];

    wmma::fragment<wmma::accumulator, 16, 16, 8, float> acc[4][2];
#pragma unroll
    for (int i = 0; i < 4; i++)
#pragma unroll
        for (int j = 0; j < 2; j++) wmma::fill_fragment(acc[i][j], 0.f);

    const int wm = (wid & 1) * 64, wn = (wid >> 1) * 32;

    for (int k0 = 0; k0 < KDIM; k0 += 32) {
        __syncthreads();
        for (int i = t; i < 1024; i += 256) {
            int row = i >> 3, k4 = (i & 7) * 4;
            *(float4*)&As[row * LDA_S + k4] =
                *(const float4*)(W + (size_t)(m0 + row) * KDIM + k0 + k4);
        }
        for (int i = t; i < 1024; i += 256) {
            int row = i >> 5, c4 = (i & 31) * 4;
            *(float4*)&Bs[row * LDB_S + c4] =
                *(const float4*)(fb + (size_t)(k0 + row) * HW + n0 + c4);
        }
        __syncthreads();
#pragma unroll
        for (int ks = 0; ks < 4; ks++) {
            wmma::fragment<wmma::matrix_a, 16, 16, 8, wmma::precision::tf32, wmma::row_major> af[4];
            wmma::fragment<wmma::matrix_b, 16, 16, 8, wmma::precision::tf32, wmma::row_major> bf[2];
#pragma unroll
            for (int mf = 0; mf < 4; mf++) {
                wmma::load_matrix_sync(af[mf], &As[(wm + mf * 16) * LDA_S + ks * 8], LDA_S);
#pragma unroll
                for (int e = 0; e < af[mf].num_elements; e++)
                    af[mf].x[e] = wmma::__float_to_tf32(af[mf].x[e]);
            }
#pragma unroll
            for (int nf = 0; nf < 2; nf++) {
                wmma::load_matrix_sync(bf[nf], &Bs[ks * 8 * LDB_S + wn + nf * 16], LDB_S);
#pragma unroll
                for (int e = 0; e < bf[nf].num_elements; e++)
                    bf[nf].x[e] = wmma::__float_to_tf32(bf[nf].x[e]);
            }
#pragma unroll
            for (int mf = 0; mf < 4; mf++)
#pragma unroll
                for (int nf = 0; nf < 2; nf++)
                    wmma::mma_sync(acc[mf][nf], af[mf], bf[nf], acc[mf][nf]);
        }
    }

    float* out = g_qkvo + ((size_t)b * M4 + m0) * NT + seg + n0;
    float* myscr = scr + wid * 256;
    const int er = lane >> 1, ec = (lane & 1) * 8;
#pragma unroll
    for (int mf = 0; mf < 4; mf++)
#pragma unroll
        for (int nf = 0; nf < 2; nf++) {
            wmma::store_matrix_sync(myscr, acc[mf][nf], 16, wmma::mem_row_major);
            __syncwarp();
            int m = wm + mf * 16 + er, n = wn + nf * 16 + ec;
            float bv = bias_sm[m];
#pragma unroll
            for (int j = 0; j < 8; j++)
                out[(size_t)m * NT + n + j] = myscr[er * 16 + ec + j] + bv;
            __syncwarp();
        }
}

// ---------------------------------------------------------------------------
// wmma tf32 proj GEMM with fused (att+lepe)*o prologue; writes d_out directly
// ---------------------------------------------------------------------------
__global__ __launch_bounds__(256) void proj_wmma_kernel(
    const float* __restrict__ Wp, const float* __restrict__ bias,
    float* __restrict__ out, int ldOut, int seg)
{
    __shared__ float As[128 * LDA_S];
    __shared__ float Bs[32 * LDB_S];
    __shared__ float bias_sm[128];
    __shared__ float scr[8 * 256];

    const int t = threadIdx.x, wid = t >> 5, lane = t & 31;
    const int m0 = blockIdx.x * 128, n0 = blockIdx.y * 128, b = blockIdx.z;

    if (t < 128) bias_sm[t] = bias[m0 + t];

    wmma::fragment<wmma::accumulator, 16, 16, 8, float> acc[4][2];
#pragma unroll
    for (int i = 0; i < 4; i++)
#pragma unroll
        for (int j = 0; j < 2; j++) wmma::fill_fragment(acc[i][j], 0.f);

    const int wm = (wid & 1) * 64, wn = (wid >> 1) * 32;

    for (int k0 = 0; k0 < KDIM; k0 += 32) {
        __syncthreads();
        for (int i = t; i < 1024; i += 256) {
            int row = i >> 3, k4 = (i & 7) * 4;
            *(float4*)&As[row * LDA_S + k4] =
                *(const float4*)(Wp + (size_t)(m0 + row) * KDIM + k0 + k4);
        }
        for (int i = t; i < 1024; i += 256) {
            int row = i >> 5, c4 = (i & 31) * 4;
            size_t ia = ((size_t)b * C + k0 + row) * NT + seg + n0 + c4;
            size_t io = ((size_t)b * M4 + 3 * C + k0 + row) * NT + seg + n0 + c4;
            float4 a4 = *(const float4*)(g_att + ia);
            float4 l4 = *(const float4*)(g_lepe + ia);
            float4 o4 = *(const float4*)(g_qkvo + io);
            float4 r;
            r.x = (a4.x + l4.x) * o4.x;
            r.y = (a4.y + l4.y) * o4.y;
            r.z = (a4.z + l4.z) * o4.z;
            r.w = (a4.w + l4.w) * o4.w;
            *(float4*)&Bs[row * LDB_S + c4] = r;
        }
        __syncthreads();
#pragma unroll
        for (int ks = 0; ks < 4; ks++) {
            wmma::fragment<wmma::matrix_a, 16, 16, 8, wmma::precision::tf32, wmma::row_major> af[4];
            wmma::fragment<wmma::matrix_b, 16, 16, 8, wmma::precision::tf32, wmma::row_major> bf[2];
#pragma unroll
            for (int mf = 0; mf < 4; mf++) {
                wmma::load_matrix_sync(af[mf], &As[(wm + mf * 16) * LDA_S + ks * 8], LDA_S);
#pragma unroll
                for (int e = 0; e < af[mf].num_elements; e++)
                    af[mf].x[e] = wmma::__float_to_tf32(af[mf].x[e]);
            }
#pragma unroll
            for (int nf = 0; nf < 2; nf++) {
                wmma::load_matrix_sync(bf[nf], &Bs[ks * 8 * LDB_S + wn + nf * 16], LDB_S);
#pragma unroll
                for (int e = 0; e < bf[nf].num_elements; e++)
                    bf[nf].x[e] = wmma::__float_to_tf32(bf[nf].x[e]);
            }
#pragma unroll
            for (int mf = 0; mf < 4; mf++)
#pragma unroll
                for (int nf = 0; nf < 2; nf++)
                    wmma::mma_sync(acc[mf][nf], af[mf], bf[nf], acc[mf][nf]);
        }
    }

    float* ob = out + ((size_t)b * C + m0) * ldOut + n0;
    float* myscr = scr + wid * 256;
    const int er = lane >> 1, ec = (lane & 1) * 8;
#pragma unroll
    for (int mf = 0; mf < 4; mf++)
#pragma unroll
        for (int nf = 0; nf < 2; nf++) {
            wmma::store_matrix_sync(myscr, acc[mf][nf], 16, wmma::mem_row_major);
            __syncwarp();
            int m = wm + mf * 16 + er, n = wn + nf * 16 + ec;
            float bv = bias_sm[m];
#pragma unroll
            for (int j = 0; j < 8; j++)
                ob[(size_t)m * ldOut + n + j] = myscr[er * 16 + ec + j] + bv;
            __syncwarp();
        }
}

// ---------------------------------------------------------------------------
// Depthwise 5x5 conv (pad 2) on v channels of g_qkvo -> g_lepe
// ---------------------------------------------------------------------------
__global__ __launch_bounds__(256) void dwconv_kernel(
    const float* __restrict__ Wl, const float* __restrict__ bl,
    int Hd, int Wd, int seg)
{
    __shared__ float tile[36 * 36];
    __shared__ float wsm[25];
    const int plane = blockIdx.x;
    const int b = plane / C, c = plane % C;
    const float* src = g_qkvo + ((size_t)b * M4 + 2 * C + c) * NT + seg;
    float* dst = g_lepe + ((size_t)b * C + c) * NT + seg;
    const int t = threadIdx.x;
    if (t < 25) wsm[t] = Wl[c * 25 + t];
    const int Wp = Wd + 4, Hp = Hd + 4, HW = Hd * Wd;
    for (int idx = t; idx < Hp * Wp; idx += 256) {
        int y = idx / Wp - 2, xq = idx % Wp - 2;
        float v = 0.f;
        if (y >= 0 && y < Hd && xq >= 0 && xq < Wd) v = src[y * Wd + xq];
        tile[idx] = v;
    }
    __syncthreads();
    float bb = bl[c];
    for (int idx = t; idx < HW; idx += 256) {
        int y = idx / Wd, xq = idx % Wd;
        float s = bb;
#pragma unroll
        for (int ky = 0; ky < 5; ky++)
#pragma unroll
            for (int kx = 0; kx < 5; kx++)
                s += wsm[ky * 5 + kx] * tile[(y + ky) * Wp + (xq + kx)];
        dst[idx] = s;
    }
}

// ---------------------------------------------------------------------------
// Flash attention, 1280-token unified sequence (scalar fp32)
// ---------------------------------------------------------------------------
__global__ __launch_bounds__(128) void attention_kernel()
{
    __shared__ float Ks[32 * 36];
    __shared__ float Vs[32 * 36];
    const int bh = blockIdx.y;
    const int b = bh / NHEADS, h = bh % NHEADS;
    const int tid = threadIdx.x;
    const int nq = blockIdx.x * 128 + tid;
    const float scale = 0.17677669529663687f;

    const float* qb = g_qkvo + ((size_t)b * M4 +         h * DHEAD) * NT;
    const float* kb = g_qkvo + ((size_t)b * M4 +     C + h * DHEAD) * NT;
    const float* vb = g_qkvo + ((size_t)b * M4 + 2 * C + h * DHEAD) * NT;

    float q[32];
#pragma unroll
    for (int dc = 0; dc < 32; dc++) q[dc] = qb[(size_t)dc * NT + nq] * scale;

    float m = -1e30f, l = 0.f;
    float acc[32];
#pragma unroll
    for (int dc = 0; dc < 32; dc++) acc[dc] = 0.f;

    for (int tkv = 0; tkv < 40; tkv++) {
        const int n0 = tkv * 32;
        __syncthreads();
        for (int idx = tid; idx < 1024; idx += 128) {
            int dc = idx >> 5, j = idx & 31;
            Ks[j * 36 + dc] = kb[(size_t)dc * NT + n0 + j];
            Vs[j * 36 + dc] = vb[(size_t)dc * NT + n0 + j];
        }
        __syncthreads();

        float s[32];
        float tmax = m;
#pragma unroll
        for (int j = 0; j < 32; j++) {
            const float4* kr = (const float4*)&Ks[j * 36];
            float sv = 0.f;
#pragma unroll
            for (int d4 = 0; d4 < 8; d4++) {
                float4 k4 = kr[d4];
                sv += q[4 * d4 + 0] * k4.x;
                sv += q[4 * d4 + 1] * k4.y;
                sv += q[4 * d4 + 2] * k4.z;
                sv += q[4 * d4 + 3] * k4.w;
            }
            s[j] = sv;
            tmax = fmaxf(tmax, sv);
        }
        float corr = __expf(m - tmax);
        m = tmax;
        l *= corr;
#pragma unroll
        for (int dc = 0; dc < 32; dc++) acc[dc] *= corr;
#pragma unroll
        for (int j = 0; j < 32; j++) {
            float p = __expf(s[j] - m);
            l += p;
            const float4* vr = (const float4*)&Vs[j * 36];
#pragma unroll
            for (int d4 = 0; d4 < 8; d4++) {
                float4 v4 = vr[d4];
                acc[4 * d4 + 0] += p * v4.x;
                acc[4 * d4 + 1] += p * v4.y;
                acc[4 * d4 + 2] += p * v4.z;
                acc[4 * d4 + 3] += p * v4.w;
            }
        }
    }

    const float inv = 1.f / l;
    float* ob = g_att + ((size_t)b * C + h * DHEAD) * NT + nq;
#pragma unroll
    for (int dc = 0; dc < 32; dc++) ob[(size_t)dc * NT] = acc[dc] * inv;
}

// ---------------------------------------------------------------------------
// Launch
// ---------------------------------------------------------------------------
extern "C" void kernel_launch(void* const* d_in, const int* in_sizes, int n_in,
                              void* d_out, int out_size)
{
    const float* z  = (const float*)d_in[0];
    const float* x  = (const float*)d_in[1];
    const float* Wq = (const float*)d_in[2];
    const float* bq = (const float*)d_in[3];
    const float* Wl = (const float*)d_in[4];
    const float* bl = (const float*)d_in[5];
    const float* Wp = (const float*)d_in[6];
    const float* bp = (const float*)d_in[7];
    float* out = (float*)d_out;

    qkvo_wmma_kernel<<<dim3(M4 / 128, NZ / 128, BATCH), 256>>>(z, NZ, 0, Wq, bq);
    qkvo_wmma_kernel<<<dim3(M4 / 128, NX / 128, BATCH), 256>>>(x, NX, NZ, Wq, bq);

    dwconv_kernel<<<BATCH * C, 256>>>(Wl, bl, 16, 16, 0);
    dwconv_kernel<<<BATCH * C, 256>>>(Wl, bl, 32, 32, NZ);

    attention_kernel<<<dim3(10, BATCH * NHEADS), 128>>>();

    proj_wmma_kernel<<<dim3(C / 128, NZ / 128, BATCH), 256>>>(Wp, bp, out, NZ, 0);
    proj_wmma_kernel<<<dim3(C / 128, NX / 128, BATCH), 256>>>(
        Wp, bp, out + (size_t)BATCH * C * NZ, NX, NZ);
}

// round 4
// speedup vs baseline: 2.0288x; 2.0288x over previous
#include <cuda_runtime.h>
#include <cstdint>

#define BATCH   8
#define C       384
#define M4      1536
#define NZ      256
#define NX      1024
#define NT      1280
#define NHEADS  12
#define DHEAD   32
#define KDIM    384

// ---------------------------------------------------------------------------
// Scratch (static device globals)
// ---------------------------------------------------------------------------
__device__ float g_qkvo[BATCH * M4 * NT];   // [b][1536][1280]
__device__ float g_lepe[BATCH * C * NT];
__device__ float g_att [BATCH * C * NT];

// ---------------------------------------------------------------------------
// tf32 helpers
// ---------------------------------------------------------------------------
__device__ __forceinline__ uint32_t f2tf32(float x) {
    uint32_t r;
    asm("cvt.rna.tf32.f32 %0, %1;" : "=r"(r) : "f"(x));
    return r;
}
__device__ __forceinline__ void mma_tf32(float* c, uint32_t a0, uint32_t a1,
                                         uint32_t a2, uint32_t a3,
                                         uint32_t b0, uint32_t b1) {
    asm volatile(
        "mma.sync.aligned.m16n8k8.row.col.f32.tf32.tf32.f32 "
        "{%0,%1,%2,%3}, {%4,%5,%6,%7}, {%8,%9}, {%0,%1,%2,%3};\n"
        : "+f"(c[0]), "+f"(c[1]), "+f"(c[2]), "+f"(c[3])
        : "r"(a0), "r"(a1), "r"(a2), "r"(a3), "r"(b0), "r"(b1));
}

// ---------------------------------------------------------------------------
// Scalar GEMM (round-1 proven): qkvo = W(1536x384) @ feat(384xHW) + bias
// 64x64 tile, 4x4 microtile, 256 threads. Output in unified NT layout.
// ---------------------------------------------------------------------------
__global__ __launch_bounds__(256) void gemm_qkvo_kernel(
    const float* __restrict__ feat, const float* __restrict__ W,
    const float* __restrict__ bias, int HW, int seg)
{
    __shared__ float As[16][64];
    __shared__ float Bs[16][64];

    const int b  = blockIdx.z;
    const int m0 = blockIdx.y * 64;
    const int n0 = blockIdx.x * 64;
    const int t  = threadIdx.x;
    const int tx = t & 15, ty = t >> 4;
    const float* fb = feat + (size_t)b * KDIM * HW;

    const int a_mm = t >> 2, a_kk = (t & 3) * 4;
    const int b_kk = t >> 4, b_nn = (t & 15) * 4;

    float acc[4][4];
#pragma unroll
    for (int i = 0; i < 4; i++)
#pragma unroll
        for (int j = 0; j < 4; j++) acc[i][j] = 0.f;

    for (int k0 = 0; k0 < KDIM; k0 += 16) {
        float4 w4 = *(const float4*)(W  + (size_t)(m0 + a_mm) * KDIM + k0 + a_kk);
        float4 f4 = *(const float4*)(fb + (size_t)(k0 + b_kk) * HW + n0 + b_nn);
        __syncthreads();
        As[a_kk + 0][a_mm] = w4.x;
        As[a_kk + 1][a_mm] = w4.y;
        As[a_kk + 2][a_mm] = w4.z;
        As[a_kk + 3][a_mm] = w4.w;
        *(float4*)&Bs[b_kk][b_nn] = f4;
        __syncthreads();
#pragma unroll
        for (int kk = 0; kk < 16; kk++) {
            float4 av = *(const float4*)&As[kk][ty * 4];
            float4 bv = *(const float4*)&Bs[kk][tx * 4];
            float a[4] = {av.x, av.y, av.z, av.w};
            float bb[4] = {bv.x, bv.y, bv.z, bv.w};
#pragma unroll
            for (int i = 0; i < 4; i++)
#pragma unroll
                for (int j = 0; j < 4; j++) acc[i][j] += a[i] * bb[j];
        }
    }

#pragma unroll
    for (int i = 0; i < 4; i++) {
        int m = m0 + ty * 4 + i;
        float bv = bias[m];
        float4 o4 = make_float4(acc[i][0] + bv, acc[i][1] + bv,
                                acc[i][2] + bv, acc[i][3] + bv);
        *(float4*)(g_qkvo + ((size_t)b * M4 + m) * NT + seg + n0 + tx * 4) = o4;
    }
}

// ---------------------------------------------------------------------------
// Scalar proj GEMM with fused (att+lepe)*o prologue; writes d_out
// ---------------------------------------------------------------------------
__global__ __launch_bounds__(256) void gemm_proj_kernel(
    const float* __restrict__ Wp, const float* __restrict__ bias,
    float* __restrict__ out, int ldOut, int seg)
{
    __shared__ float As[16][64];
    __shared__ float Bs[16][64];

    const int b  = blockIdx.z;
    const int m0 = blockIdx.y * 64;
    const int n0 = blockIdx.x * 64;
    const int t  = threadIdx.x;
    const int tx = t & 15, ty = t >> 4;

    const int a_mm = t >> 2, a_kk = (t & 3) * 4;
    const int b_kk = t >> 4, b_nn = (t & 15) * 4;

    float acc[4][4];
#pragma unroll
    for (int i = 0; i < 4; i++)
#pragma unroll
        for (int j = 0; j < 4; j++) acc[i][j] = 0.f;

    for (int k0 = 0; k0 < KDIM; k0 += 16) {
        float4 w4 = *(const float4*)(Wp + (size_t)(m0 + a_mm) * KDIM + k0 + a_kk);
        size_t ia = ((size_t)b * C + k0 + b_kk) * NT + seg + n0 + b_nn;
        size_t io = ((size_t)b * M4 + 3 * C + k0 + b_kk) * NT + seg + n0 + b_nn;
        float4 a4 = *(const float4*)(g_att + ia);
        float4 l4 = *(const float4*)(g_lepe + ia);
        float4 o4 = *(const float4*)(g_qkvo + io);
        float4 f4 = make_float4((a4.x + l4.x) * o4.x, (a4.y + l4.y) * o4.y,
                                (a4.z + l4.z) * o4.z, (a4.w + l4.w) * o4.w);
        __syncthreads();
        As[a_kk + 0][a_mm] = w4.x;
        As[a_kk + 1][a_mm] = w4.y;
        As[a_kk + 2][a_mm] = w4.z;
        As[a_kk + 3][a_mm] = w4.w;
        *(float4*)&Bs[b_kk][b_nn] = f4;
        __syncthreads();
#pragma unroll
        for (int kk = 0; kk < 16; kk++) {
            float4 av = *(const float4*)&As[kk][ty * 4];
            float4 bv = *(const float4*)&Bs[kk][tx * 4];
            float a[4] = {av.x, av.y, av.z, av.w};
            float bb[4] = {bv.x, bv.y, bv.z, bv.w};
#pragma unroll
            for (int i = 0; i < 4; i++)
#pragma unroll
                for (int j = 0; j < 4; j++) acc[i][j] += a[i] * bb[j];
        }
    }

#pragma unroll
    for (int i = 0; i < 4; i++) {
        int m = m0 + ty * 4 + i;
        float bv = bias[m];
        float4 o4 = make_float4(acc[i][0] + bv, acc[i][1] + bv,
                                acc[i][2] + bv, acc[i][3] + bv);
        *(float4*)(out + ((size_t)b * C + m) * ldOut + n0 + tx * 4) = o4;
    }
}

// ---------------------------------------------------------------------------
// Depthwise 5x5 conv on v channels of g_qkvo -> g_lepe
// ---------------------------------------------------------------------------
__global__ __launch_bounds__(256) void dwconv_kernel(
    const float* __restrict__ Wl, const float* __restrict__ bl,
    int Hd, int Wd, int seg)
{
    __shared__ float tile[36 * 36];
    __shared__ float wsm[25];
    const int plane = blockIdx.x;
    const int b = plane / C, c = plane % C;
    const float* src = g_qkvo + ((size_t)b * M4 + 2 * C + c) * NT + seg;
    float* dst = g_lepe + ((size_t)b * C + c) * NT + seg;
    const int t = threadIdx.x;
    if (t < 25) wsm[t] = Wl[c * 25 + t];
    const int Wp = Wd + 4, Hp = Hd + 4, HW = Hd * Wd;
    for (int idx = t; idx < Hp * Wp; idx += 256) {
        int y = idx / Wp - 2, xq = idx % Wp - 2;
        float v = 0.f;
        if (y >= 0 && y < Hd && xq >= 0 && xq < Wd) v = src[y * Wd + xq];
        tile[idx] = v;
    }
    __syncthreads();
    float bb = bl[c];
    for (int idx = t; idx < HW; idx += 256) {
        int y = idx / Wd, xq = idx % Wd;
        float s = bb;
#pragma unroll
        for (int ky = 0; ky < 5; ky++)
#pragma unroll
            for (int kx = 0; kx < 5; kx++)
                s += wsm[ky * 5 + kx] * tile[(y + ky) * Wp + (xq + kx)];
        dst[idx] = s;
    }
}

// ---------------------------------------------------------------------------
// tf32 mma.sync flash attention.
// Grid (10, 96): 128 queries per CTA, 8 warps x 16 rows; Bc=64 keys/tile.
// Smem (floats): Ks[32][76] @0, Vs[32][76] @2432, BIG @4864:
//   BIG holds Q stage [32][136] during prologue, then per-warp P [16][76].
// ---------------------------------------------------------------------------
#define ATT_LD   76
#define KS_F     0
#define VS_F     2432
#define BIG_F    4864
#define PS_WARP  1216                       // 16*76 floats per warp
#define ATT_SMEM ((BIG_F + 8 * PS_WARP) * 4)   // 58368 bytes

__global__ __launch_bounds__(256) void attention_kernel()
{
    extern __shared__ float smf[];
    uint32_t* Ksu = (uint32_t*)(smf + KS_F);
    uint32_t* Vsu = (uint32_t*)(smf + VS_F);

    const int tid = threadIdx.x;
    const int w   = tid >> 5, lane = tid & 31;
    const int g   = lane >> 2, tq = lane & 3;
    const int bh  = blockIdx.y;
    const int b   = bh / NHEADS, h = bh % NHEADS;
    const int nq0 = blockIdx.x * 128;
    const int wq0 = w * 16;
    const float scale = 0.17677669529663687f;

    const float* qb = g_qkvo + ((size_t)b * M4 +         h * DHEAD) * NT;
    const float* kb = g_qkvo + ((size_t)b * M4 +     C + h * DHEAD) * NT;
    const float* vb = g_qkvo + ((size_t)b * M4 + 2 * C + h * DHEAD) * NT;

    // ---- stage Q [32 d][128 n] (ld 136), then extract A fragments ----
    {
        float* Qs = smf + BIG_F;
        for (int i = tid; i < 4096; i += 256) {
            int d = i >> 7, n = i & 127;
            Qs[d * 136 + n] = qb[(size_t)d * NT + nq0 + n];
        }
    }
    __syncthreads();
    uint32_t qa[4][4];
    {
        const float* Qs = smf + BIG_F;
#pragma unroll
        for (int kc = 0; kc < 4; kc++) {
            qa[kc][0] = f2tf32(Qs[(kc * 8 + tq) * 136 + wq0 + g] * scale);
            qa[kc][1] = f2tf32(Qs[(kc * 8 + tq) * 136 + wq0 + g + 8] * scale);
            qa[kc][2] = f2tf32(Qs[(kc * 8 + tq + 4) * 136 + wq0 + g] * scale);
            qa[kc][3] = f2tf32(Qs[(kc * 8 + tq + 4) * 136 + wq0 + g + 8] * scale);
        }
    }

    float mA = -1e30f, mB = -1e30f, lA = 0.f, lB = 0.f;
    float oacc[4][4];
#pragma unroll
    for (int i = 0; i < 4; i++)
#pragma unroll
        for (int j = 0; j < 4; j++) oacc[i][j] = 0.f;

    uint32_t* Psu = (uint32_t*)(smf + BIG_F) + w * PS_WARP;

    for (int tile = 0; tile < 20; tile++) {
        const int tok0 = tile * 64;
        __syncthreads();                       // prev-tile smem reads done
        for (int i = tid; i < 2048; i += 256) {
            int d = i >> 6, j = i & 63;
            Ksu[d * ATT_LD + j] = f2tf32(kb[(size_t)d * NT + tok0 + j]);
            Vsu[d * ATT_LD + j] = f2tf32(vb[(size_t)d * NT + tok0 + j]);
        }
        __syncthreads();

        // ---- S = Q K^T : 8 n-frags of 8 tokens ----
        float s[8][4];
#pragma unroll
        for (int nf = 0; nf < 8; nf++)
#pragma unroll
            for (int j = 0; j < 4; j++) s[nf][j] = 0.f;
#pragma unroll
        for (int kc = 0; kc < 4; kc++)
#pragma unroll
            for (int nf = 0; nf < 8; nf++) {
                uint32_t b0 = Ksu[(kc * 8 + tq) * ATT_LD + nf * 8 + g];
                uint32_t b1 = Ksu[(kc * 8 + tq + 4) * ATT_LD + nf * 8 + g];
                mma_tf32(s[nf], qa[kc][0], qa[kc][1], qa[kc][2], qa[kc][3], b0, b1);
            }

        // ---- online softmax (rows g and g+8) ----
        float vA = -1e30f, vB = -1e30f;
#pragma unroll
        for (int nf = 0; nf < 8; nf++) {
            vA = fmaxf(vA, fmaxf(s[nf][0], s[nf][1]));
            vB = fmaxf(vB, fmaxf(s[nf][2], s[nf][3]));
        }
        vA = fmaxf(vA, __shfl_xor_sync(0xffffffffu, vA, 1));
        vA = fmaxf(vA, __shfl_xor_sync(0xffffffffu, vA, 2));
        vB = fmaxf(vB, __shfl_xor_sync(0xffffffffu, vB, 1));
        vB = fmaxf(vB, __shfl_xor_sync(0xffffffffu, vB, 2));
        float mAn = fmaxf(mA, vA), mBn = fmaxf(mB, vB);
        float cA = __expf(mA - mAn), cB = __expf(mB - mBn);
        mA = mAn; mB = mBn;
        lA *= cA; lB *= cB;
#pragma unroll
        for (int nf2 = 0; nf2 < 4; nf2++) {
            oacc[nf2][0] *= cA; oacc[nf2][1] *= cA;
            oacc[nf2][2] *= cB; oacc[nf2][3] *= cB;
        }
#pragma unroll
        for (int nf = 0; nf < 8; nf++) {
            float p0 = __expf(s[nf][0] - mA);
            float p1 = __expf(s[nf][1] - mA);
            float p2 = __expf(s[nf][2] - mB);
            float p3 = __expf(s[nf][3] - mB);
            lA += p0 + p1;  lB += p2 + p3;
            int colb = nf * 8 + 2 * tq;
            Psu[g * ATT_LD + colb]           = f2tf32(p0);
            Psu[g * ATT_LD + colb + 1]       = f2tf32(p1);
            Psu[(g + 8) * ATT_LD + colb]     = f2tf32(p2);
            Psu[(g + 8) * ATT_LD + colb + 1] = f2tf32(p3);
        }
        __syncwarp();

        // ---- O += P V : 8 k-frags of 8 tokens, 4 d-frags ----
#pragma unroll
        for (int kf = 0; kf < 8; kf++) {
            uint32_t a0 = Psu[g * ATT_LD + kf * 8 + tq];
            uint32_t a1 = Psu[(g + 8) * ATT_LD + kf * 8 + tq];
            uint32_t a2 = Psu[g * ATT_LD + kf * 8 + tq + 4];
            uint32_t a3 = Psu[(g + 8) * ATT_LD + kf * 8 + tq + 4];
#pragma unroll
            for (int nf2 = 0; nf2 < 4; nf2++) {
                uint32_t b0 = Vsu[(nf2 * 8 + g) * ATT_LD + kf * 8 + tq];
                uint32_t b1 = Vsu[(nf2 * 8 + g) * ATT_LD + kf * 8 + tq + 4];
                mma_tf32(oacc[nf2], a0, a1, a2, a3, b0, b1);
            }
        }
        __syncwarp();
    }

    // ---- finalize ----
    lA += __shfl_xor_sync(0xffffffffu, lA, 1);
    lA += __shfl_xor_sync(0xffffffffu, lA, 2);
    lB += __shfl_xor_sync(0xffffffffu, lB, 1);
    lB += __shfl_xor_sync(0xffffffffu, lB, 2);
    float iA = 1.f / lA, iB = 1.f / lB;

    float* ob = g_att + ((size_t)b * C + h * DHEAD) * NT;
    const int nA = nq0 + wq0 + g, nB = nA + 8;
#pragma unroll
    for (int nf2 = 0; nf2 < 4; nf2++) {
        int d0 = nf2 * 8 + 2 * tq;
        ob[(size_t)d0 * NT + nA]       = oacc[nf2][0] * iA;
        ob[(size_t)(d0 + 1) * NT + nA] = oacc[nf2][1] * iA;
        ob[(size_t)d0 * NT + nB]       = oacc[nf2][2] * iB;
        ob[(size_t)(d0 + 1) * NT + nB] = oacc[nf2][3] * iB;
    }
}

// ---------------------------------------------------------------------------
// Launch
// ---------------------------------------------------------------------------
extern "C" void kernel_launch(void* const* d_in, const int* in_sizes, int n_in,
                              void* d_out, int out_size)
{
    const float* z  = (const float*)d_in[0];
    const float* x  = (const float*)d_in[1];
    const float* Wq = (const float*)d_in[2];
    const float* bq = (const float*)d_in[3];
    const float* Wl = (const float*)d_in[4];
    const float* bl = (const float*)d_in[5];
    const float* Wp = (const float*)d_in[6];
    const float* bp = (const float*)d_in[7];
    float* out = (float*)d_out;

    cudaFuncSetAttribute(attention_kernel,
                         cudaFuncAttributeMaxDynamicSharedMemorySize, ATT_SMEM);

    gemm_qkvo_kernel<<<dim3(NZ / 64, M4 / 64, BATCH), 256>>>(z, Wq, bq, NZ, 0);
    gemm_qkvo_kernel<<<dim3(NX / 64, M4 / 64, BATCH), 256>>>(x, Wq, bq, NX, NZ);

    dwconv_kernel<<<BATCH * C, 256>>>(Wl, bl, 16, 16, 0);
    dwconv_kernel<<<BATCH * C, 256>>>(Wl, bl, 32, 32, NZ);

    attention_kernel<<<dim3(10, BATCH * NHEADS), 256, ATT_SMEM>>>();

    gemm_proj_kernel<<<dim3(NZ / 64, C / 64, BATCH), 256>>>(Wp, bp, out, NZ, 0);
    gemm_proj_kernel<<<dim3(NX / 64, C / 64, BATCH), 256>>>(
        Wp, bp, out + (size_t)BATCH * C * NZ, NX, NZ);
}

// round 5
// speedup vs baseline: 2.0310x; 1.0011x over previous
#include <cuda_runtime.h>
#include <cstdint>

#define BATCH   8
#define C       384
#define M4      1536
#define NZ      256
#define NX      1024
#define NT      1280
#define NHEADS  12
#define DHEAD   32
#define KDIM    384

// ---------------------------------------------------------------------------
// Scratch (static device globals)
// ---------------------------------------------------------------------------
__device__ float g_qkvo[BATCH * M4 * NT];   // [b][1536][1280]
__device__ float g_lepe[BATCH * C * NT];
__device__ float g_att [BATCH * C * NT];

// ---------------------------------------------------------------------------
// tf32 helpers
// ---------------------------------------------------------------------------
__device__ __forceinline__ uint32_t f2tf32(float x) {
    uint32_t r;
    asm("cvt.rna.tf32.f32 %0, %1;" : "=r"(r) : "f"(x));
    return r;
}
__device__ __forceinline__ void mma_tf32(float* c, uint32_t a0, uint32_t a1,
                                         uint32_t a2, uint32_t a3,
                                         uint32_t b0, uint32_t b1) {
    asm volatile(
        "mma.sync.aligned.m16n8k8.row.col.f32.tf32.tf32.f32 "
        "{%0,%1,%2,%3}, {%4,%5,%6,%7}, {%8,%9}, {%0,%1,%2,%3};\n"
        : "+f"(c[0]), "+f"(c[1]), "+f"(c[2]), "+f"(c[3])
        : "r"(a0), "r"(a1), "r"(a2), "r"(a3), "r"(b0), "r"(b1));
}

// ---------------------------------------------------------------------------
// Scalar GEMM (round-1 proven): qkvo = W(1536x384) @ feat(384xHW) + bias
// 64x64 tile, 4x4 microtile, 256 threads. Output in unified NT layout.
// ---------------------------------------------------------------------------
__global__ __launch_bounds__(256) void gemm_qkvo_kernel(
    const float* __restrict__ feat, const float* __restrict__ W,
    const float* __restrict__ bias, int HW, int seg)
{
    __shared__ float As[16][64];
    __shared__ float Bs[16][64];

    const int b  = blockIdx.z;
    const int m0 = blockIdx.y * 64;
    const int n0 = blockIdx.x * 64;
    const int t  = threadIdx.x;
    const int tx = t & 15, ty = t >> 4;
    const float* fb = feat + (size_t)b * KDIM * HW;

    const int a_mm = t >> 2, a_kk = (t & 3) * 4;
    const int b_kk = t >> 4, b_nn = (t & 15) * 4;

    float acc[4][4];
#pragma unroll
    for (int i = 0; i < 4; i++)
#pragma unroll
        for (int j = 0; j < 4; j++) acc[i][j] = 0.f;

    for (int k0 = 0; k0 < KDIM; k0 += 16) {
        float4 w4 = *(const float4*)(W  + (size_t)(m0 + a_mm) * KDIM + k0 + a_kk);
        float4 f4 = *(const float4*)(fb + (size_t)(k0 + b_kk) * HW + n0 + b_nn);
        __syncthreads();
        As[a_kk + 0][a_mm] = w4.x;
        As[a_kk + 1][a_mm] = w4.y;
        As[a_kk + 2][a_mm] = w4.z;
        As[a_kk + 3][a_mm] = w4.w;
        *(float4*)&Bs[b_kk][b_nn] = f4;
        __syncthreads();
#pragma unroll
        for (int kk = 0; kk < 16; kk++) {
            float4 av = *(const float4*)&As[kk][ty * 4];
            float4 bv = *(const float4*)&Bs[kk][tx * 4];
            float a[4] = {av.x, av.y, av.z, av.w};
            float bb[4] = {bv.x, bv.y, bv.z, bv.w};
#pragma unroll
            for (int i = 0; i < 4; i++)
#pragma unroll
                for (int j = 0; j < 4; j++) acc[i][j] += a[i] * bb[j];
        }
    }

#pragma unroll
    for (int i = 0; i < 4; i++) {
        int m = m0 + ty * 4 + i;
        float bv = bias[m];
        float4 o4 = make_float4(acc[i][0] + bv, acc[i][1] + bv,
                                acc[i][2] + bv, acc[i][3] + bv);
        *(float4*)(g_qkvo + ((size_t)b * M4 + m) * NT + seg + n0 + tx * 4) = o4;
    }
}

// ---------------------------------------------------------------------------
// Scalar proj GEMM with fused (att+lepe)*o prologue; writes d_out
// ---------------------------------------------------------------------------
__global__ __launch_bounds__(256) void gemm_proj_kernel(
    const float* __restrict__ Wp, const float* __restrict__ bias,
    float* __restrict__ out, int ldOut, int seg)
{
    __shared__ float As[16][64];
    __shared__ float Bs[16][64];

    const int b  = blockIdx.z;
    const int m0 = blockIdx.y * 64;
    const int n0 = blockIdx.x * 64;
    const int t  = threadIdx.x;
    const int tx = t & 15, ty = t >> 4;

    const int a_mm = t >> 2, a_kk = (t & 3) * 4;
    const int b_kk = t >> 4, b_nn = (t & 15) * 4;

    float acc[4][4];
#pragma unroll
    for (int i = 0; i < 4; i++)
#pragma unroll
        for (int j = 0; j < 4; j++) acc[i][j] = 0.f;

    for (int k0 = 0; k0 < KDIM; k0 += 16) {
        float4 w4 = *(const float4*)(Wp + (size_t)(m0 + a_mm) * KDIM + k0 + a_kk);
        size_t ia = ((size_t)b * C + k0 + b_kk) * NT + seg + n0 + b_nn;
        size_t io = ((size_t)b * M4 + 3 * C + k0 + b_kk) * NT + seg + n0 + b_nn;
        float4 a4 = *(const float4*)(g_att + ia);
        float4 l4 = *(const float4*)(g_lepe + ia);
        float4 o4 = *(const float4*)(g_qkvo + io);
        float4 f4 = make_float4((a4.x + l4.x) * o4.x, (a4.y + l4.y) * o4.y,
                                (a4.z + l4.z) * o4.z, (a4.w + l4.w) * o4.w);
        __syncthreads();
        As[a_kk + 0][a_mm] = w4.x;
        As[a_kk + 1][a_mm] = w4.y;
        As[a_kk + 2][a_mm] = w4.z;
        As[a_kk + 3][a_mm] = w4.w;
        *(float4*)&Bs[b_kk][b_nn] = f4;
        __syncthreads();
#pragma unroll
        for (int kk = 0; kk < 16; kk++) {
            float4 av = *(const float4*)&As[kk][ty * 4];
            float4 bv = *(const float4*)&Bs[kk][tx * 4];
            float a[4] = {av.x, av.y, av.z, av.w};
            float bb[4] = {bv.x, bv.y, bv.z, bv.w};
#pragma unroll
            for (int i = 0; i < 4; i++)
#pragma unroll
                for (int j = 0; j < 4; j++) acc[i][j] += a[i] * bb[j];
        }
    }

#pragma unroll
    for (int i = 0; i < 4; i++) {
        int m = m0 + ty * 4 + i;
        float bv = bias[m];
        float4 o4 = make_float4(acc[i][0] + bv, acc[i][1] + bv,
                                acc[i][2] + bv, acc[i][3] + bv);
        *(float4*)(out + ((size_t)b * C + m) * ldOut + n0 + tx * 4) = o4;
    }
}

// ---------------------------------------------------------------------------
// Depthwise 5x5 conv on v channels of g_qkvo -> g_lepe
// ---------------------------------------------------------------------------
__global__ __launch_bounds__(256) void dwconv_kernel(
    const float* __restrict__ Wl, const float* __restrict__ bl,
    int Hd, int Wd, int seg)
{
    __shared__ float tile[36 * 36];
    __shared__ float wsm[25];
    const int plane = blockIdx.x;
    const int b = plane / C, c = plane % C;
    const float* src = g_qkvo + ((size_t)b * M4 + 2 * C + c) * NT + seg;
    float* dst = g_lepe + ((size_t)b * C + c) * NT + seg;
    const int t = threadIdx.x;
    if (t < 25) wsm[t] = Wl[c * 25 + t];
    const int Wp = Wd + 4, Hp = Hd + 4, HW = Hd * Wd;
    for (int idx = t; idx < Hp * Wp; idx += 256) {
        int y = idx / Wp - 2, xq = idx % Wp - 2;
        float v = 0.f;
        if (y >= 0 && y < Hd && xq >= 0 && xq < Wd) v = src[y * Wd + xq];
        tile[idx] = v;
    }
    __syncthreads();
    float bb = bl[c];
    for (int idx = t; idx < HW; idx += 256) {
        int y = idx / Wd, xq = idx % Wd;
        float s = bb;
#pragma unroll
        for (int ky = 0; ky < 5; ky++)
#pragma unroll
            for (int kx = 0; kx < 5; kx++)
                s += wsm[ky * 5 + kx] * tile[(y + ky) * Wp + (xq + kx)];
        dst[idx] = s;
    }
}

// ---------------------------------------------------------------------------
// tf32 mma.sync flash attention.
// Grid (10, 96): 128 queries per CTA, 8 warps x 16 rows; Bc=64 keys/tile.
// Smem (floats): Ks[32][76] @0, Vs[32][76] @2432, BIG @4864:
//   BIG holds Q stage [32][136] during prologue, then per-warp P [16][76].
// ---------------------------------------------------------------------------
#define ATT_LD   76
#define KS_F     0
#define VS_F     2432
#define BIG_F    4864
#define PS_WARP  1216                       // 16*76 floats per warp
#define ATT_SMEM ((BIG_F + 8 * PS_WARP) * 4)   // 58368 bytes

__global__ __launch_bounds__(256) void attention_kernel()
{
    extern __shared__ float smf[];
    uint32_t* Ksu = (uint32_t*)(smf + KS_F);
    uint32_t* Vsu = (uint32_t*)(smf + VS_F);

    const int tid = threadIdx.x;
    const int w   = tid >> 5, lane = tid & 31;
    const int g   = lane >> 2, tq = lane & 3;
    const int bh  = blockIdx.y;
    const int b   = bh / NHEADS, h = bh % NHEADS;
    const int nq0 = blockIdx.x * 128;
    const int wq0 = w * 16;
    const float scale = 0.17677669529663687f;

    const float* qb = g_qkvo + ((size_t)b * M4 +         h * DHEAD) * NT;
    const float* kb = g_qkvo + ((size_t)b * M4 +     C + h * DHEAD) * NT;
    const float* vb = g_qkvo + ((size_t)b * M4 + 2 * C + h * DHEAD) * NT;

    // ---- stage Q [32 d][128 n] (ld 136), then extract A fragments ----
    {
        float* Qs = smf + BIG_F;
        for (int i = tid; i < 4096; i += 256) {
            int d = i >> 7, n = i & 127;
            Qs[d * 136 + n] = qb[(size_t)d * NT + nq0 + n];
        }
    }
    __syncthreads();
    uint32_t qa[4][4];
    {
        const float* Qs = smf + BIG_F;
#pragma unroll
        for (int kc = 0; kc < 4; kc++) {
            qa[kc][0] = f2tf32(Qs[(kc * 8 + tq) * 136 + wq0 + g] * scale);
            qa[kc][1] = f2tf32(Qs[(kc * 8 + tq) * 136 + wq0 + g + 8] * scale);
            qa[kc][2] = f2tf32(Qs[(kc * 8 + tq + 4) * 136 + wq0 + g] * scale);
            qa[kc][3] = f2tf32(Qs[(kc * 8 + tq + 4) * 136 + wq0 + g + 8] * scale);
        }
    }

    float mA = -1e30f, mB = -1e30f, lA = 0.f, lB = 0.f;
    float oacc[4][4];
#pragma unroll
    for (int i = 0; i < 4; i++)
#pragma unroll
        for (int j = 0; j < 4; j++) oacc[i][j] = 0.f;

    uint32_t* Psu = (uint32_t*)(smf + BIG_F) + w * PS_WARP;

    for (int tile = 0; tile < 20; tile++) {
        const int tok0 = tile * 64;
        __syncthreads();                       // prev-tile smem reads done
        for (int i = tid; i < 2048; i += 256) {
            int d = i >> 6, j = i & 63;
            Ksu[d * ATT_LD + j] = f2tf32(kb[(size_t)d * NT + tok0 + j]);
            Vsu[d * ATT_LD + j] = f2tf32(vb[(size_t)d * NT + tok0 + j]);
        }
        __syncthreads();

        // ---- S = Q K^T : 8 n-frags of 8 tokens ----
        float s[8][4];
#pragma unroll
        for (int nf = 0; nf < 8; nf++)
#pragma unroll
            for (int j = 0; j < 4; j++) s[nf][j] = 0.f;
#pragma unroll
        for (int kc = 0; kc < 4; kc++)
#pragma unroll
            for (int nf = 0; nf < 8; nf++) {
                uint32_t b0 = Ksu[(kc * 8 + tq) * ATT_LD + nf * 8 + g];
                uint32_t b1 = Ksu[(kc * 8 + tq + 4) * ATT_LD + nf * 8 + g];
                mma_tf32(s[nf], qa[kc][0], qa[kc][1], qa[kc][2], qa[kc][3], b0, b1);
            }

        // ---- online softmax (rows g and g+8) ----
        float vA = -1e30f, vB = -1e30f;
#pragma unroll
        for (int nf = 0; nf < 8; nf++) {
            vA = fmaxf(vA, fmaxf(s[nf][0], s[nf][1]));
            vB = fmaxf(vB, fmaxf(s[nf][2], s[nf][3]));
        }
        vA = fmaxf(vA, __shfl_xor_sync(0xffffffffu, vA, 1));
        vA = fmaxf(vA, __shfl_xor_sync(0xffffffffu, vA, 2));
        vB = fmaxf(vB, __shfl_xor_sync(0xffffffffu, vB, 1));
        vB = fmaxf(vB, __shfl_xor_sync(0xffffffffu, vB, 2));
        float mAn = fmaxf(mA, vA), mBn = fmaxf(mB, vB);
        float cA = __expf(mA - mAn), cB = __expf(mB - mBn);
        mA = mAn; mB = mBn;
        lA *= cA; lB *= cB;
#pragma unroll
        for (int nf2 = 0; nf2 < 4; nf2++) {
            oacc[nf2][0] *= cA; oacc[nf2][1] *= cA;
            oacc[nf2][2] *= cB; oacc[nf2][3] *= cB;
        }
#pragma unroll
        for (int nf = 0; nf < 8; nf++) {
            float p0 = __expf(s[nf][0] - mA);
            float p1 = __expf(s[nf][1] - mA);
            float p2 = __expf(s[nf][2] - mB);
            float p3 = __expf(s[nf][3] - mB);
            lA += p0 + p1;  lB += p2 + p3;
            int colb = nf * 8 + 2 * tq;
            Psu[g * ATT_LD + colb]           = f2tf32(p0);
            Psu[g * ATT_LD + colb + 1]       = f2tf32(p1);
            Psu[(g + 8) * ATT_LD + colb]     = f2tf32(p2);
            Psu[(g + 8) * ATT_LD + colb + 1] = f2tf32(p3);
        }
        __syncwarp();

        // ---- O += P V : 8 k-frags of 8 tokens, 4 d-frags ----
#pragma unroll
        for (int kf = 0; kf < 8; kf++) {
            uint32_t a0 = Psu[g * ATT_LD + kf * 8 + tq];
            uint32_t a1 = Psu[(g + 8) * ATT_LD + kf * 8 + tq];
            uint32_t a2 = Psu[g * ATT_LD + kf * 8 + tq + 4];
            uint32_t a3 = Psu[(g + 8) * ATT_LD + kf * 8 + tq + 4];
#pragma unroll
            for (int nf2 = 0; nf2 < 4; nf2++) {
                uint32_t b0 = Vsu[(nf2 * 8 + g) * ATT_LD + kf * 8 + tq];
                uint32_t b1 = Vsu[(nf2 * 8 + g) * ATT_LD + kf * 8 + tq + 4];
                mma_tf32(oacc[nf2], a0, a1, a2, a3, b0, b1);
            }
        }
        __syncwarp();
    }

    // ---- finalize ----
    lA += __shfl_xor_sync(0xffffffffu, lA, 1);
    lA += __shfl_xor_sync(0xffffffffu, lA, 2);
    lB += __shfl_xor_sync(0xffffffffu, lB, 1);
    lB += __shfl_xor_sync(0xffffffffu, lB, 2);
    float iA = 1.f / lA, iB = 1.f / lB;

    float* ob = g_att + ((size_t)b * C + h * DHEAD) * NT;
    const int nA = nq0 + wq0 + g, nB = nA + 8;
#pragma unroll
    for (int nf2 = 0; nf2 < 4; nf2++) {
        int d0 = nf2 * 8 + 2 * tq;
        ob[(size_t)d0 * NT + nA]       = oacc[nf2][0] * iA;
        ob[(size_t)(d0 + 1) * NT + nA] = oacc[nf2][1] * iA;
        ob[(size_t)d0 * NT + nB]       = oacc[nf2][2] * iB;
        ob[(size_t)(d0 + 1) * NT + nB] = oacc[nf2][3] * iB;
    }
}

// ---------------------------------------------------------------------------
// Launch
// ---------------------------------------------------------------------------
extern "C" void kernel_launch(void* const* d_in, const int* in_sizes, int n_in,
                              void* d_out, int out_size)
{
    const float* z  = (const float*)d_in[0];
    const float* x  = (const float*)d_in[1];
    const float* Wq = (const float*)d_in[2];
    const float* bq = (const float*)d_in[3];
    const float* Wl = (const float*)d_in[4];
    const float* bl = (const float*)d_in[5];
    const float* Wp = (const float*)d_in[6];
    const float* bp = (const float*)d_in[7];
    float* out = (float*)d_out;

    cudaFuncSetAttribute(attention_kernel,
                         cudaFuncAttributeMaxDynamicSharedMemorySize, ATT_SMEM);

    gemm_qkvo_kernel<<<dim3(NZ / 64, M4 / 64, BATCH), 256>>>(z, Wq, bq, NZ, 0);
    gemm_qkvo_kernel<<<dim3(NX / 64, M4 / 64, BATCH), 256>>>(x, Wq, bq, NX, NZ);

    dwconv_kernel<<<BATCH * C, 256>>>(Wl, bl, 16, 16, 0);
    dwconv_kernel<<<BATCH * C, 256>>>(Wl, bl, 32, 32, NZ);

    attention_kernel<<<dim3(10, BATCH * NHEADS), 256, ATT_SMEM>>>();

    gemm_proj_kernel<<<dim3(NZ / 64, C / 64, BATCH), 256>>>(Wp, bp, out, NZ, 0);
    gemm_proj_kernel<<<dim3(NX / 64, C / 64, BATCH), 256>>>(
        Wp, bp, out + (size_t)BATCH * C * NZ, NX, NZ);
}